// round 16
// baseline (speedup 1.0000x reference)
#include <cuda_runtime.h>
#include <math.h>
#include <cstdint>

#define BB 8
#define NN 2048
#define CC 512
#define KK 8
#define EPSF 1e-6f
#define GENO_RATIO 0.1f

// ---------------- scratch ----------------
__device__ int   g_cnt[BB][KK];
__device__ int   g_idx[BB][KK][NN];
__device__ float g_wgt[BB][KK][NN];
__device__ float g_mass[BB][KK];
__device__ float g_hw[BB][KK][CC];
__device__ float g_glog[BB][KK];
__device__ uint32_t g_xbf[BB * NN * (CC / 2)];   // tokens as bf16x2 rows (16MB)
__device__ uint32_t g_w1p[KK * (CC / 2) * CC];   // w1 k-pair-interleaved bf16x2 (4MB)

__device__ __forceinline__ uint32_t bf16x2(float lo, float hi) {
    uint32_t r;
    asm("cvt.rn.bf16x2.f32 %0, %1, %2;" : "=r"(r) : "f"(hi), "f"(lo));
    return r;
}
__device__ __forceinline__ uint32_t smem_u32(const void* p) {
    uint32_t a;
    asm("{ .reg .u64 t; cvta.to.shared.u64 t, %1; cvt.u32.u64 %0, t; }" : "=r"(a) : "l"(p));
    return a;
}
__device__ __forceinline__ void cpasync16(uint32_t dst, const void* src, uint32_t sz) {
    asm volatile("cp.async.cg.shared.global [%0], [%1], 16, %2;" :: "r"(dst), "l"(src), "r"(sz));
}
__device__ __forceinline__ void cpasync16f(uint32_t dst, const void* src) {
    asm volatile("cp.async.cg.shared.global [%0], [%1], 16;" :: "r"(dst), "l"(src));
}

// ---------------- prep: pack w1 + zero hw/cnt/mass + glog ----------------
__global__ __launch_bounds__(256) void prep_kernel(const float* __restrict__ w1,
                                                   const float* __restrict__ geno_vec,
                                                   const float* __restrict__ geno_w,
                                                   const float* __restrict__ geno_b) {
    int bid = blockIdx.x;
    if (bid < 512) {
        int k = bid >> 6;
        int c2b = (bid & 63) * 4;
        int t = threadIdx.x;
#pragma unroll
        for (int r = 0; r < 4; r++) {
            int c2 = c2b + r;
            const float* src = w1 + ((size_t)k * CC + 2 * c2) * CC;
            uint32_t* dst = g_w1p + ((size_t)k * (CC / 2) + c2) * CC;
#pragma unroll
            for (int h = 0; h < 2; h++) {
                int d = t + h * 256;
                dst[d] = bf16x2(src[d], src[CC + d]);
            }
        }
    } else if (bid < 544) {
        int t = (bid - 512) * 256 + threadIdx.x;
        float* hw = &g_hw[0][0][0];
#pragma unroll
        for (int i = 0; i < 4; i++) hw[t + i * 8192] = 0.f;
    } else {
        int t = threadIdx.x;
        if (t < BB * KK) {
            ((int*)g_cnt)[t] = 0;
            ((float*)g_mass)[t] = 0.f;
            int b = t / KK, k = t % KK;
            float acc = 0.f;
            for (int c = 0; c < CC; c++) acc += geno_vec[b * CC + c] * geno_w[c * KK + k];
            g_glog[b][k] = GENO_RATIO * (acc + geno_b[k]);
        }
    }
}

// ---------------- gating (+ fused bf16 token conversion) ----------------
__global__ __launch_bounds__(256) void gate_kernel(const float* __restrict__ tokens,
                                                   const float* __restrict__ gate_w,
                                                   const float* __restrict__ gate_b) {
    __shared__ float gwT[KK][CC];
    int tid = threadIdx.x;
    for (int i = tid; i < CC * KK; i += 256) gwT[i & 7][i >> 3] = gate_w[i];
    __syncthreads();

    int warp = blockIdx.x * 8 + (tid >> 5);
    int lane = tid & 31;
    if (warp >= BB * NN) return;
    int b = warp / NN, n = warp % NN;
    const float* x = tokens + (size_t)(b * NN + n) * CC;
    uint32_t* xo = g_xbf + (size_t)(b * NN + n) * (CC / 2);

    float acc[KK];
#pragma unroll
    for (int k = 0; k < KK; k++) acc[k] = 0.f;
#pragma unroll
    for (int i = 0; i < 4; i++) {
        int c = i * 128 + lane * 4;
        float4 xv = *(const float4*)(x + c);
        uint2 pk;
        pk.x = bf16x2(xv.x, xv.y);
        pk.y = bf16x2(xv.z, xv.w);
        *(uint2*)(xo + c / 2) = pk;
#pragma unroll
        for (int k = 0; k < KK; k++) {
            float4 gv = *(const float4*)&gwT[k][c];
            acc[k] += xv.x * gv.x + xv.y * gv.y + xv.z * gv.z + xv.w * gv.w;
        }
    }
#pragma unroll
    for (int k = 0; k < KK; k++) {
#pragma unroll
        for (int off = 16; off; off >>= 1)
            acc[k] += __shfl_xor_sync(0xffffffffu, acc[k], off);
    }

    if (lane == 0) {
        float lg[KK];
#pragma unroll
        for (int k = 0; k < KK; k++) lg[k] = acc[k] + gate_b[k] + g_glog[b][k];
        int i0 = 0; float v0 = lg[0];
#pragma unroll
        for (int k = 1; k < KK; k++) if (lg[k] > v0) { v0 = lg[k]; i0 = k; }
        int i1 = -1; float v1 = -3.4e38f;
#pragma unroll
        for (int k = 0; k < KK; k++) if (k != i0 && lg[k] > v1) { v1 = lg[k]; i1 = k; }
        float e1 = __expf(v1 - v0);
        float inv = 1.f / (1.f + e1);
        float w0 = fmaxf(inv, EPSF), w1v = fmaxf(e1 * inv, EPSF);
        float s = 1.f / (w0 + w1v);
        w0 *= s; w1v *= s;
        int p0 = atomicAdd(&g_cnt[b][i0], 1);
        g_idx[b][i0][p0] = n; g_wgt[b][i0][p0] = w0;
        atomicAdd(&g_mass[b][i0], w0);
        int p1 = atomicAdd(&g_cnt[b][i1], 1);
        g_idx[b][i1][p1] = n; g_wgt[b][i1][p1] = w1v;
        atomicAdd(&g_mass[b][i1], w1v);
    }
}

// ---------------- ffn1: bf16 mma, cp.async 4-stage pipeline, 1 sync/stage -------
#define BM 128
#define BN 256
#define NSTAGE 16
#define XS_STR 20                    // u32 per X row ([m][k2]); conflict-free
#define WS_STR 264                   // u32 per W row ([k2][n]); proven
#define X_U32 (BM * XS_STR)          // 2560
#define W_U32 (16 * WS_STR)          // 4224
#define STAGE_U32 (X_U32 + W_U32)    // 6784
#define SMEM_BYTES (4 * STAGE_U32 * 4 + BM * 8)

__device__ __forceinline__ void mma16816(float* c, const uint32_t* a, const uint32_t* bf) {
    asm volatile(
        "mma.sync.aligned.m16n8k16.row.col.f32.bf16.bf16.f32 "
        "{%0,%1,%2,%3}, {%4,%5,%6,%7}, {%8,%9}, {%0,%1,%2,%3};"
        : "+f"(c[0]), "+f"(c[1]), "+f"(c[2]), "+f"(c[3])
        : "r"(a[0]), "r"(a[1]), "r"(a[2]), "r"(a[3]), "r"(bf[0]), "r"(bf[1]));
}

__global__ __launch_bounds__(256, 1) void ffn1_mma_kernel(const float* __restrict__ b1) {
    extern __shared__ uint32_t smem[];
    const int bk = blockIdx.z;
    const int b = bk >> 3, k = bk & 7;
    const int cnt = g_cnt[b][k];
    const int m0 = blockIdx.y * BM;
    if (m0 >= cnt) return;
    const int d0 = blockIdx.x * BN;

    int*   ns_s = (int*)(smem + 4 * STAGE_U32);
    float* wt_s = (float*)(ns_s + BM);

    const int tid = threadIdx.x;
    const int lane = tid & 31, wid = tid >> 5;
    const int wm = wid >> 2, wn = wid & 3;     // 2m x 4n warp grid, 64x64 tiles
    const int l4 = lane >> 2, lm = lane & 3;

    if (tid < BM) {
        int m = m0 + tid;
        if (m < cnt) { ns_s[tid] = g_idx[b][k][m]; wt_s[tid] = g_wgt[b][k][m]; }
        else         { ns_s[tid] = -1;             wt_s[tid] = 0.f; }
    }
    __syncthreads();

    const uint32_t sbase = smem_u32(smem);

    // X loader: row xm = tid&127, 32B half xo = (tid>>7)*8
    const int xm = tid & 127;
    const int xo = (tid >> 7) * 8;
    const int xn = ns_s[xm];
    const uint32_t* xp = (xn >= 0) ? g_xbf + (size_t)(b * NN + xn) * (CC / 2) : g_xbf;
    const uint32_t xsz = (xn >= 0) ? 16u : 0u;
    // W loader: k2 row wr2 = tid>>4 (0..15), n-chunk base wn4 = (tid&15)*4
    const int wr2 = tid >> 4;
    const int wn4 = (tid & 15) * 4;
    const uint32_t* wpp = g_w1p + (size_t)k * (CC / 2) * CC + d0 + wn4;

    const uint32_t xdoff = (xm * XS_STR + xo) * 4;
    const uint32_t wdoff = X_U32 * 4 + (wr2 * WS_STR + wn4) * 4;

#define ISSUE_STAGE(s) do {                                                       \
        uint32_t sb_ = sbase + ((s) & 3) * (STAGE_U32 * 4);                       \
        const uint32_t* xs_ = xp + (s) * 16 + xo;                                 \
        cpasync16(sb_ + xdoff,      xs_,     xsz);                                \
        cpasync16(sb_ + xdoff + 16, xs_ + 4, xsz);                                \
        const uint32_t* ws_ = wpp + (size_t)((s) * 16 + wr2) * CC;                \
        _Pragma("unroll")                                                         \
        for (int i = 0; i < 4; i++)                                               \
            cpasync16f(sb_ + wdoff + i * 256, ws_ + i * 64);                      \
        asm volatile("cp.async.commit_group;" ::: "memory");                      \
    } while (0)

    float acc[4][8][4];
#pragma unroll
    for (int mf = 0; mf < 4; mf++)
#pragma unroll
        for (int nf = 0; nf < 8; nf++)
#pragma unroll
            for (int q = 0; q < 4; q++) acc[mf][nf][q] = 0.f;

    ISSUE_STAGE(0);
    ISSUE_STAGE(1);
    ISSUE_STAGE(2);

    for (int s = 0; s < NSTAGE; s++) {
        if (s + 3 < NSTAGE)
            asm volatile("cp.async.wait_group 2;" ::: "memory");
        else
            asm volatile("cp.async.wait_group 0;" ::: "memory");
        __syncthreads();

        const uint32_t* Xst = smem + (s & 3) * STAGE_U32;
        const uint32_t* Wst = Xst + X_U32;

#pragma unroll
        for (int c = 0; c < 2; c++) {           // two k16 chunks per 32-k stage
            uint32_t a[4][4], bf[8][2];
#pragma unroll
            for (int mf = 0; mf < 4; mf++) {
                const uint32_t* xr = Xst + (wm * 64 + mf * 16 + l4) * XS_STR + c * 8 + lm;
                a[mf][0] = xr[0];
                a[mf][1] = xr[8 * XS_STR];
                a[mf][2] = xr[4];
                a[mf][3] = xr[8 * XS_STR + 4];
            }
            const uint32_t* wk0 = Wst + (c * 8 + lm) * WS_STR;
            const uint32_t* wk4 = Wst + (c * 8 + 4 + lm) * WS_STR;
#pragma unroll
            for (int nf = 0; nf < 8; nf++) {
                int ncol = wn * 64 + nf * 8 + l4;
                bf[nf][0] = wk0[ncol];
                bf[nf][1] = wk4[ncol];
            }
#pragma unroll
            for (int mf = 0; mf < 4; mf++)
#pragma unroll
                for (int nf = 0; nf < 8; nf++)
                    mma16816(acc[mf][nf], a[mf], bf[nf]);
        }

        if (s + 3 < NSTAGE) ISSUE_STAGE(s + 3);
    }

    // epilogue: relu(acc + b1) * wt, reduce over token rows
    float bias[8][2];
#pragma unroll
    for (int nf = 0; nf < 8; nf++)
#pragma unroll
        for (int j = 0; j < 2; j++)
            bias[nf][j] = __ldg(b1 + k * CC + d0 + wn * 64 + nf * 8 + lm * 2 + j);

    float part[8][2];
#pragma unroll
    for (int nf = 0; nf < 8; nf++) { part[nf][0] = 0.f; part[nf][1] = 0.f; }

#pragma unroll
    for (int mf = 0; mf < 4; mf++) {
        int r0 = wm * 64 + mf * 16 + l4;
        float w0 = wt_s[r0], w1r = wt_s[r0 + 8];
#pragma unroll
        for (int nf = 0; nf < 8; nf++)
#pragma unroll
            for (int j = 0; j < 2; j++)
                part[nf][j] += fmaxf(acc[mf][nf][j] + bias[nf][j], 0.f) * w0
                             + fmaxf(acc[mf][nf][2 + j] + bias[nf][j], 0.f) * w1r;
    }
#pragma unroll
    for (int off = 4; off < 32; off <<= 1)
#pragma unroll
        for (int nf = 0; nf < 8; nf++)
#pragma unroll
            for (int j = 0; j < 2; j++)
                part[nf][j] += __shfl_xor_sync(0xffffffffu, part[nf][j], off);

    if (l4 == 0) {
        float* hw = &g_hw[b][k][0];
#pragma unroll
        for (int nf = 0; nf < 8; nf++)
#pragma unroll
            for (int j = 0; j < 2; j++)
                atomicAdd(hw + d0 + wn * 64 + nf * 8 + lm * 2 + j, part[nf][j]);
    }
}

// ---------------- centers: batched over b, w2 read once (+loss fused) ----------
__global__ __launch_bounds__(256) void centers_kernel(const float* __restrict__ w2,
                                                      const float* __restrict__ b2,
                                                      float* __restrict__ out, int out_size) {
    const int k = blockIdx.x;
    const int e0 = blockIdx.y * 32;
    __shared__ float hw_s[BB][CC];
    __shared__ float part[8][32][9];
    const int tid = threadIdx.x;

    for (int i = tid; i < BB * CC; i += 256)
        hw_s[i >> 9][i & 511] = g_hw[i >> 9][k][i & 511];
    __syncthreads();

    const int e = e0 + (tid & 31);
    const int ds = (tid >> 5) * 64;
    float acc[BB];
#pragma unroll
    for (int b = 0; b < BB; b++) acc[b] = 0.f;

    const float* w2p = w2 + ((size_t)k * CC + ds) * CC + e;
#pragma unroll 16
    for (int d = 0; d < 64; d++) {
        float w = w2p[(size_t)d * CC];
#pragma unroll
        for (int b = 0; b < BB; b++) acc[b] += hw_s[b][ds + d] * w;
    }
#pragma unroll
    for (int b = 0; b < BB; b++) part[tid >> 5][tid & 31][b] = acc[b];
    __syncthreads();

    {
        const int b = tid >> 5, el = tid & 31;
        float s = 0.f;
#pragma unroll
        for (int sl = 0; sl < 8; sl++) s += part[sl][el][b];
        float mass = g_mass[b][k];
        float inv = 1.f / fmaxf(mass, EPSF);
        float val = (s + b2[k * CC + e0 + el] * mass) * inv;
        int o = (b * KK + k) * CC + e0 + el;
        if (o < out_size) out[o] = val;
    }

    if (blockIdx.x == 0 && blockIdx.y == 0 && tid == 0) {
        float usage[KK], mean = 0.f;
#pragma unroll
        for (int kk = 0; kk < KK; kk++) {
            int s = 0;
            for (int bb = 0; bb < BB; bb++) s += g_cnt[bb][kk];
            usage[kk] = (float)s / (float)(BB * NN);
            mean += usage[kk];
        }
        mean /= (float)KK;
        float var = 0.f;
#pragma unroll
        for (int kk = 0; kk < KK; kk++) { float d = usage[kk] - mean; var += d * d; }
        var /= (float)KK;
        float denom = mean + EPSF;
        out[out_size - 1] = var / (denom * denom);
    }
}

// ---------------- launch ----------------
extern "C" void kernel_launch(void* const* d_in, const int* in_sizes, int n_in,
                              void* d_out, int out_size) {
    const float* tokens   = (const float*)d_in[0];
    const float* geno_vec = (const float*)d_in[1];
    const float* gate_w   = (const float*)d_in[2];
    const float* gate_b   = (const float*)d_in[3];
    const float* geno_w   = (const float*)d_in[4];
    const float* geno_b   = (const float*)d_in[5];
    const float* w1       = (const float*)d_in[6];
    const float* b1       = (const float*)d_in[7];
    const float* w2       = (const float*)d_in[8];
    const float* b2       = (const float*)d_in[9];
    float* out = (float*)d_out;

    cudaFuncSetAttribute(ffn1_mma_kernel, cudaFuncAttributeMaxDynamicSharedMemorySize, SMEM_BYTES);

    prep_kernel<<<545, 256>>>(w1, geno_vec, geno_w, geno_b);
    gate_kernel<<<(BB * NN + 7) / 8, 256>>>(tokens, gate_w, gate_b);
    {
        dim3 g(CC / BN, NN / BM, BB * KK);  // 2 x 16 x 64
        ffn1_mma_kernel<<<g, 256, SMEM_BYTES>>>(b1);
    }
    {
        dim3 g(KK, CC / 32);
        centers_kernel<<<g, 256>>>(w2, b2, out, out_size);
    }
}

// round 17
// speedup vs baseline: 1.0677x; 1.0677x over previous
#include <cuda_runtime.h>
#include <math.h>
#include <cstdint>

#define BB 8
#define NN 2048
#define CC 512
#define KK 8
#define EPSF 1e-6f
#define GENO_RATIO 0.1f

// ---------------- scratch ----------------
__device__ int   g_cnt[BB][KK];
__device__ int   g_idx[BB][KK][NN];
__device__ float g_wgt[BB][KK][NN];
__device__ float g_mass[BB][KK];
__device__ float g_hw[BB][KK][CC];
__device__ uint32_t g_xbf[BB * NN * (CC / 2)];   // tokens as bf16x2 rows (16MB)
__device__ uint32_t g_w1p[KK * (CC / 2) * CC];   // w1 k-pair-interleaved bf16x2 (4MB)

__device__ __forceinline__ uint32_t bf16x2(float lo, float hi) {
    uint32_t r;
    asm("cvt.rn.bf16x2.f32 %0, %1, %2;" : "=r"(r) : "f"(hi), "f"(lo));
    return r;
}

// ---------------- prep: zero hw/cnt/mass only ----------------
__global__ __launch_bounds__(256) void prep_kernel() {
    if (blockIdx.x < 32) {
        int t = blockIdx.x * 256 + threadIdx.x;
        float* hw = &g_hw[0][0][0];
#pragma unroll
        for (int i = 0; i < 4; i++) hw[t + i * 8192] = 0.f;
    } else {
        int t = threadIdx.x;
        if (t < BB * KK) {
            ((int*)g_cnt)[t] = 0;
            ((float*)g_mass)[t] = 0.f;
        }
    }
}

// ---------------- gate (inline geno) + w1 pack, fused by grid partition -------
__global__ __launch_bounds__(256) void gatepack_kernel(const float* __restrict__ tokens,
                                                       const float* __restrict__ gate_w,
                                                       const float* __restrict__ gate_b,
                                                       const float* __restrict__ geno_vec,
                                                       const float* __restrict__ geno_w,
                                                       const float* __restrict__ geno_b,
                                                       const float* __restrict__ w1) {
    const int bid = blockIdx.x;
    const int tid = threadIdx.x;

    if (bid >= (BB * NN) / 8) {
        // ---- w1 pack role: w1p[k][c2][d] = bf16x2(w1[k][2c2][d], w1[k][2c2+1][d])
        int pbid = bid - (BB * NN) / 8;     // 0..511
        int k = pbid >> 6;
        int c2b = (pbid & 63) * 4;
#pragma unroll
        for (int r = 0; r < 4; r++) {
            int c2 = c2b + r;
            const float* src = w1 + ((size_t)k * CC + 2 * c2) * CC;
            uint32_t* dst = g_w1p + ((size_t)k * (CC / 2) + c2) * CC;
#pragma unroll
            for (int h = 0; h < 2; h++) {
                int d = tid + h * 256;
                dst[d] = bf16x2(src[d], src[CC + d]);
            }
        }
        return;
    }

    // ---- gate role ----
    __shared__ float gwT[KK][CC];   // transposed gate weights
    __shared__ float gnT[KK][CC];   // transposed geno weights
    for (int i = tid; i < CC * KK; i += 256) {
        gwT[i & 7][i >> 3] = gate_w[i];
        gnT[i & 7][i >> 3] = geno_w[i];
    }
    __syncthreads();

    int warp = bid * 8 + (tid >> 5);
    int lane = tid & 31;
    int b = warp / NN, n = warp % NN;
    const float* x = tokens + (size_t)(b * NN + n) * CC;
    const float* gv = geno_vec + (size_t)b * CC;
    uint32_t* xo = g_xbf + (size_t)(b * NN + n) * (CC / 2);

    float acc[KK], accg[KK];
#pragma unroll
    for (int k = 0; k < KK; k++) { acc[k] = 0.f; accg[k] = 0.f; }
#pragma unroll
    for (int i = 0; i < 4; i++) {
        int c = i * 128 + lane * 4;
        float4 xv = *(const float4*)(x + c);
        float4 gvv = *(const float4*)(gv + c);
        uint2 pk;
        pk.x = bf16x2(xv.x, xv.y);
        pk.y = bf16x2(xv.z, xv.w);
        *(uint2*)(xo + c / 2) = pk;
#pragma unroll
        for (int k = 0; k < KK; k++) {
            float4 wv = *(const float4*)&gwT[k][c];
            acc[k] += xv.x * wv.x + xv.y * wv.y + xv.z * wv.z + xv.w * wv.w;
            float4 nv = *(const float4*)&gnT[k][c];
            accg[k] += gvv.x * nv.x + gvv.y * nv.y + gvv.z * nv.z + gvv.w * nv.w;
        }
    }
#pragma unroll
    for (int k = 0; k < KK; k++) {
#pragma unroll
        for (int off = 16; off; off >>= 1) {
            acc[k]  += __shfl_xor_sync(0xffffffffu, acc[k], off);
            accg[k] += __shfl_xor_sync(0xffffffffu, accg[k], off);
        }
    }

    if (lane == 0) {
        float lg[KK];
#pragma unroll
        for (int k = 0; k < KK; k++)
            lg[k] = acc[k] + gate_b[k] + GENO_RATIO * (accg[k] + geno_b[k]);
        int i0 = 0; float v0 = lg[0];
#pragma unroll
        for (int k = 1; k < KK; k++) if (lg[k] > v0) { v0 = lg[k]; i0 = k; }
        int i1 = -1; float v1 = -3.4e38f;
#pragma unroll
        for (int k = 0; k < KK; k++) if (k != i0 && lg[k] > v1) { v1 = lg[k]; i1 = k; }
        float e1 = __expf(v1 - v0);
        float inv = 1.f / (1.f + e1);
        float w0 = fmaxf(inv, EPSF), w1v = fmaxf(e1 * inv, EPSF);
        float s = 1.f / (w0 + w1v);
        w0 *= s; w1v *= s;
        int p0 = atomicAdd(&g_cnt[b][i0], 1);
        g_idx[b][i0][p0] = n; g_wgt[b][i0][p0] = w0;
        atomicAdd(&g_mass[b][i0], w0);
        int p1 = atomicAdd(&g_cnt[b][i1], 1);
        g_idx[b][i1][p1] = n; g_wgt[b][i1][p1] = w1v;
        atomicAdd(&g_mass[b][i1], w1v);
    }
}

// ---------------- ffn1: bf16 m16n8k16, pre-packed global, LDG staging (R15) -----
#define BM 128
#define BN 256
#define NSTAGE 16
#define XS2_STRIDE (BM + 8)     // 136 u32
#define WS2_STRIDE (BN + 8)     // 264 u32
#define X2_U32 (16 * XS2_STRIDE)   // 2176
#define W2_U32 (16 * WS2_STRIDE)   // 4224
#define STAGE_U32 (X2_U32 + W2_U32)
#define SMEM_BYTES (2 * STAGE_U32 * 4 + BM * 8)

__device__ __forceinline__ void mma16816(float* c, const uint32_t* a, const uint32_t* bf) {
    asm volatile(
        "mma.sync.aligned.m16n8k16.row.col.f32.bf16.bf16.f32 "
        "{%0,%1,%2,%3}, {%4,%5,%6,%7}, {%8,%9}, {%0,%1,%2,%3};"
        : "+f"(c[0]), "+f"(c[1]), "+f"(c[2]), "+f"(c[3])
        : "r"(a[0]), "r"(a[1]), "r"(a[2]), "r"(a[3]), "r"(bf[0]), "r"(bf[1]));
}

__global__ __launch_bounds__(256, 1) void ffn1_mma_kernel(const float* __restrict__ b1) {
    extern __shared__ uint32_t smem[];
    const int bk = blockIdx.z;
    const int b = bk >> 3, k = bk & 7;
    const int cnt = g_cnt[b][k];
    const int m0 = blockIdx.y * BM;
    if (m0 >= cnt) return;
    const int d0 = blockIdx.x * BN;

    uint32_t* Xs0 = smem;
    uint32_t* Ws0 = smem + X2_U32;
    uint32_t* Xs1 = smem + STAGE_U32;
    uint32_t* Ws1 = smem + STAGE_U32 + X2_U32;
    int*   ns_s = (int*)(smem + 2 * STAGE_U32);
    float* wt_s = (float*)(ns_s + BM);

    const int tid = threadIdx.x;
    const int lane = tid & 31, wid = tid >> 5;
    const int wm = wid >> 2, wn = wid & 3;     // 2m x 4n warp grid, 64x64 tiles
    const int l4 = lane >> 2, lm = lane & 3;

    if (tid < BM) {
        int m = m0 + tid;
        if (m < cnt) { ns_s[tid] = g_idx[b][k][m]; wt_s[tid] = g_wgt[b][k][m]; }
        else         { ns_s[tid] = -1;             wt_s[tid] = 0.f; }
    }
    __syncthreads();

    const int xm = tid >> 1;
    const int xh = (tid & 1) * 8;
    const int xn = ns_s[xm];
    const uint32_t* xp = (xn >= 0) ? g_xbf + (size_t)(b * NN + xn) * (CC / 2) : nullptr;
    const int wr2 = tid >> 4;
    const int wn4 = (tid & 15) * 4;
    const uint32_t* wpp = g_w1p + (size_t)k * (CC / 2) * CC + d0 + wn4;

    uint4 xa, xb, wq[4];
#define LOAD_STAGE(s) do {                                                        \
        const uint32_t* xr_ = xp + (s) * 16 + xh;                                 \
        if (xp) { xa = *(const uint4*)xr_; xb = *(const uint4*)(xr_ + 4); }       \
        else { xa = make_uint4(0,0,0,0); xb = xa; }                               \
        const uint32_t* wr_ = wpp + (size_t)((s) * 16 + wr2) * CC;                \
        _Pragma("unroll")                                                         \
        for (int i = 0; i < 4; i++) wq[i] = *(const uint4*)(wr_ + i * 64);        \
    } while (0)

#define STORE_STAGE(Xst, Wst) do {                                                \
        (Xst)[(xh + 0) * XS2_STRIDE + xm] = xa.x;                                 \
        (Xst)[(xh + 1) * XS2_STRIDE + xm] = xa.y;                                 \
        (Xst)[(xh + 2) * XS2_STRIDE + xm] = xa.z;                                 \
        (Xst)[(xh + 3) * XS2_STRIDE + xm] = xa.w;                                 \
        (Xst)[(xh + 4) * XS2_STRIDE + xm] = xb.x;                                 \
        (Xst)[(xh + 5) * XS2_STRIDE + xm] = xb.y;                                 \
        (Xst)[(xh + 6) * XS2_STRIDE + xm] = xb.z;                                 \
        (Xst)[(xh + 7) * XS2_STRIDE + xm] = xb.w;                                 \
        _Pragma("unroll")                                                         \
        for (int i = 0; i < 4; i++)                                               \
            *(uint4*)((Wst) + wr2 * WS2_STRIDE + wn4 + i * 64) = wq[i];           \
    } while (0)

    float acc[4][8][4];
#pragma unroll
    for (int mf = 0; mf < 4; mf++)
#pragma unroll
        for (int nf = 0; nf < 8; nf++)
#pragma unroll
            for (int q = 0; q < 4; q++) acc[mf][nf][q] = 0.f;

    LOAD_STAGE(0);
    STORE_STAGE(Xs0, Ws0);
    __syncthreads();

    for (int s = 0; s < NSTAGE; s++) {
        const uint32_t* Xst = (s & 1) ? Xs1 : Xs0;
        const uint32_t* Wst = (s & 1) ? Ws1 : Ws0;
        if (s + 1 < NSTAGE) LOAD_STAGE(s + 1);

#pragma unroll
        for (int c = 0; c < 2; c++) {
            uint32_t a[4][4], bf[8][2];
            const uint32_t* xk0 = Xst + (c * 8 + lm) * XS2_STRIDE;
            const uint32_t* xk4 = Xst + (c * 8 + 4 + lm) * XS2_STRIDE;
#pragma unroll
            for (int mf = 0; mf < 4; mf++) {
                int mrow = wm * 64 + mf * 16 + l4;
                a[mf][0] = xk0[mrow];
                a[mf][1] = xk0[mrow + 8];
                a[mf][2] = xk4[mrow];
                a[mf][3] = xk4[mrow + 8];
            }
            const uint32_t* wk0 = Wst + (c * 8 + lm) * WS2_STRIDE;
            const uint32_t* wk4 = Wst + (c * 8 + 4 + lm) * WS2_STRIDE;
#pragma unroll
            for (int nf = 0; nf < 8; nf++) {
                int ncol = wn * 64 + nf * 8 + l4;
                bf[nf][0] = wk0[ncol];
                bf[nf][1] = wk4[ncol];
            }
#pragma unroll
            for (int mf = 0; mf < 4; mf++)
#pragma unroll
                for (int nf = 0; nf < 8; nf++)
                    mma16816(acc[mf][nf], a[mf], bf[nf]);
        }

        if (s + 1 < NSTAGE) {
            __syncthreads();
            if (s & 1) STORE_STAGE(Xs0, Ws0);
            else       STORE_STAGE(Xs1, Ws1);
            __syncthreads();
        }
    }

    // epilogue: relu(acc + b1) * wt, reduce over token rows
    float bias[8][2];
#pragma unroll
    for (int nf = 0; nf < 8; nf++)
#pragma unroll
        for (int j = 0; j < 2; j++)
            bias[nf][j] = __ldg(b1 + k * CC + d0 + wn * 64 + nf * 8 + lm * 2 + j);

    float part[8][2];
#pragma unroll
    for (int nf = 0; nf < 8; nf++) { part[nf][0] = 0.f; part[nf][1] = 0.f; }

#pragma unroll
    for (int mf = 0; mf < 4; mf++) {
        int r0 = wm * 64 + mf * 16 + l4;
        float w0 = wt_s[r0], w1r = wt_s[r0 + 8];
#pragma unroll
        for (int nf = 0; nf < 8; nf++)
#pragma unroll
            for (int j = 0; j < 2; j++)
                part[nf][j] += fmaxf(acc[mf][nf][j] + bias[nf][j], 0.f) * w0
                             + fmaxf(acc[mf][nf][2 + j] + bias[nf][j], 0.f) * w1r;
    }
#pragma unroll
    for (int off = 4; off < 32; off <<= 1)
#pragma unroll
        for (int nf = 0; nf < 8; nf++)
#pragma unroll
            for (int j = 0; j < 2; j++)
                part[nf][j] += __shfl_xor_sync(0xffffffffu, part[nf][j], off);

    if (l4 == 0) {
        float* hw = &g_hw[b][k][0];
#pragma unroll
        for (int nf = 0; nf < 8; nf++)
#pragma unroll
            for (int j = 0; j < 2; j++)
                atomicAdd(hw + d0 + wn * 64 + nf * 8 + lm * 2 + j, part[nf][j]);
    }
}

// ---------------- centers: 512 threads, 16 d-slices x 32 e (+loss fused) --------
__global__ __launch_bounds__(512) void centers_kernel(const float* __restrict__ w2,
                                                      const float* __restrict__ b2,
                                                      float* __restrict__ out, int out_size) {
    const int k = blockIdx.x;
    const int e0 = blockIdx.y * 32;
    __shared__ float hw_s[BB][CC];       // 16KB
    __shared__ float part[16][32][9];    // 18KB, padded
    const int tid = threadIdx.x;

    for (int i = tid; i < BB * CC; i += 512)
        hw_s[i >> 9][i & 511] = g_hw[i >> 9][k][i & 511];
    __syncthreads();

    const int e = e0 + (tid & 31);
    const int ds = (tid >> 5) * 32;      // 16 slices of 32 d
    float acc[BB];
#pragma unroll
    for (int b = 0; b < BB; b++) acc[b] = 0.f;

    const float* w2p = w2 + ((size_t)k * CC + ds) * CC + e;
#pragma unroll 16
    for (int d = 0; d < 32; d++) {
        float w = w2p[(size_t)d * CC];
#pragma unroll
        for (int b = 0; b < BB; b++) acc[b] += hw_s[b][ds + d] * w;
    }
#pragma unroll
    for (int b = 0; b < BB; b++) part[tid >> 5][tid & 31][b] = acc[b];
    __syncthreads();

    if (tid < 256) {
        const int b = tid >> 5, el = tid & 31;
        float s = 0.f;
#pragma unroll
        for (int sl = 0; sl < 16; sl++) s += part[sl][el][b];
        float mass = g_mass[b][k];
        float inv = 1.f / fmaxf(mass, EPSF);
        float val = (s + b2[k * CC + e0 + el] * mass) * inv;
        int o = (b * KK + k) * CC + e0 + el;
        if (o < out_size) out[o] = val;
    }

    if (blockIdx.x == 0 && blockIdx.y == 0 && tid == 0) {
        float usage[KK], mean = 0.f;
#pragma unroll
        for (int kk = 0; kk < KK; kk++) {
            int s = 0;
            for (int bb = 0; bb < BB; bb++) s += g_cnt[bb][kk];
            usage[kk] = (float)s / (float)(BB * NN);
            mean += usage[kk];
        }
        mean /= (float)KK;
        float var = 0.f;
#pragma unroll
        for (int kk = 0; kk < KK; kk++) { float d = usage[kk] - mean; var += d * d; }
        var /= (float)KK;
        float denom = mean + EPSF;
        out[out_size - 1] = var / (denom * denom);
    }
}

// ---------------- launch ----------------
extern "C" void kernel_launch(void* const* d_in, const int* in_sizes, int n_in,
                              void* d_out, int out_size) {
    const float* tokens   = (const float*)d_in[0];
    const float* geno_vec = (const float*)d_in[1];
    const float* gate_w   = (const float*)d_in[2];
    const float* gate_b   = (const float*)d_in[3];
    const float* geno_w   = (const float*)d_in[4];
    const float* geno_b   = (const float*)d_in[5];
    const float* w1       = (const float*)d_in[6];
    const float* b1       = (const float*)d_in[7];
    const float* w2       = (const float*)d_in[8];
    const float* b2       = (const float*)d_in[9];
    float* out = (float*)d_out;

    cudaFuncSetAttribute(ffn1_mma_kernel, cudaFuncAttributeMaxDynamicSharedMemorySize, SMEM_BYTES);

    prep_kernel<<<33, 256>>>();
    gatepack_kernel<<<(BB * NN) / 8 + 512, 256>>>(tokens, gate_w, gate_b,
                                                  geno_vec, geno_w, geno_b, w1);
    {
        dim3 g(CC / BN, NN / BM, BB * KK);  // 2 x 16 x 64
        ffn1_mma_kernel<<<g, 256, SMEM_BYTES>>>(b1);
    }
    {
        dim3 g(KK, CC / 32);
        centers_kernel<<<g, 512>>>(w2, b2, out, out_size);
    }
}